// round 2
// baseline (speedup 1.0000x reference)
#include <cuda_runtime.h>

// NodeConvolution: out[b,s,d] = x[b,2s,d]*w[0,d] + x[b,2s+1,d]*w[1,d]
// B=32, N=4096, D=512, P=2  ->  out [32, 2048, 512] fp32
// Streaming, HBM-bound: 256 MiB read + 128 MiB write.
//
// Each thread computes TWO output rows at one D-offset (float4 granularity):
//   out[2r  ][d..d+3] and out[2r+1][d..d+3]
// -> 4 independent x float4-loads per thread (MLP=4), w0/w1 reused twice.

#define D4      128   // D/4 float4s per row
#define THREADS 256

__global__ __launch_bounds__(THREADS)
void nodeconv_kernel(const float4* __restrict__ x,
                     const float4* __restrict__ w,
                     float4* __restrict__ out,
                     int pair4)            // = total output float4s / 2
{
    int j = blockIdx.x * THREADS + threadIdx.x;
    if (j >= pair4) return;

    int d4 = j & (D4 - 1);       // D-offset in float4 units
    int rr = j >> 7;             // pair index: output rows 2rr, 2rr+1

    // Output row k consumes input rows 2k, 2k+1.
    const float4* xr = x + (size_t)rr * (4 * D4);   // input row 4rr
    // Front-batch all global loads for maximum MLP.
    float4 a0 = xr[0 * D4 + d4];   // x row 4rr
    float4 b0 = xr[1 * D4 + d4];   // x row 4rr+1
    float4 a1 = xr[2 * D4 + d4];   // x row 4rr+2
    float4 b1 = xr[3 * D4 + d4];   // x row 4rr+3
    float4 w0 = __ldg(&w[d4]);
    float4 w1 = __ldg(&w[D4 + d4]);

    float4 r0, r1;
    r0.x = fmaf(a0.x, w0.x, b0.x * w1.x);
    r0.y = fmaf(a0.y, w0.y, b0.y * w1.y);
    r0.z = fmaf(a0.z, w0.z, b0.z * w1.z);
    r0.w = fmaf(a0.w, w0.w, b0.w * w1.w);
    r1.x = fmaf(a1.x, w0.x, b1.x * w1.x);
    r1.y = fmaf(a1.y, w0.y, b1.y * w1.y);
    r1.z = fmaf(a1.z, w0.z, b1.z * w1.z);
    r1.w = fmaf(a1.w, w0.w, b1.w * w1.w);

    float4* orow = out + (size_t)rr * (2 * D4);
    orow[d4]      = r0;
    orow[D4 + d4] = r1;
}

extern "C" void kernel_launch(void* const* d_in, const int* in_sizes, int n_in,
                              void* d_out, int out_size)
{
    const float4* x = (const float4*)d_in[0];   // [B, N, D] fp32
    const float4* w = (const float4*)d_in[1];   // [P, D] fp32
    float4* out     = (float4*)d_out;           // [B, N/P, D] fp32

    int pair4  = out_size / 8;                  // output float4s / 2 rows-per-thread
    int blocks = (pair4 + THREADS - 1) / THREADS;

    nodeconv_kernel<<<blocks, THREADS>>>(x, w, out, pair4);
}

// round 4
// speedup vs baseline: 1.0005x; 1.0005x over previous
#include <cuda_runtime.h>

// NodeConvolution: out[b,s,d] = x[b,2s,d]*w[0,d] + x[b,2s+1,d]*w[1,d]
// B=32, N=4096, D=512, P=2  ->  out [32, 2048, 512] fp32
// Streaming, HBM-bound: 256 MiB read + 128 MiB write. Roofline ~44 us kernel.
//
// Each thread computes FOUR output rows at one D-offset (float4 granularity):
// 8 independent front-batched x loads (high MLP), weights reused 4x,
// streaming cache hints (.cs) since x/out are touched exactly once.

#define D4      128   // D/4 float4s per row
#define THREADS 256

__global__ __launch_bounds__(THREADS)
void nodeconv_kernel(const float4* __restrict__ x,
                     const float4* __restrict__ w,
                     float4* __restrict__ out,
                     int quad4)            // = total output float4s / 4
{
    int j = blockIdx.x * THREADS + threadIdx.x;
    if (j >= quad4) return;

    int d4 = j & (D4 - 1);       // D-offset in float4 units
    int rq = j >> 7;             // quad index: output rows 4rq..4rq+3

    // Output row k consumes input rows 2k, 2k+1 -> input rows 8rq..8rq+7.
    const float4* xr = x + (size_t)rq * (8 * D4) + d4;

    // Front-batch all 8 x loads for maximum outstanding-sector depth.
    float4 a0 = __ldcs(xr + 0 * D4);
    float4 b0 = __ldcs(xr + 1 * D4);
    float4 a1 = __ldcs(xr + 2 * D4);
    float4 b1 = __ldcs(xr + 3 * D4);
    float4 a2 = __ldcs(xr + 4 * D4);
    float4 b2 = __ldcs(xr + 5 * D4);
    float4 a3 = __ldcs(xr + 6 * D4);
    float4 b3 = __ldcs(xr + 7 * D4);
    float4 w0 = __ldg(&w[d4]);
    float4 w1 = __ldg(&w[D4 + d4]);

    float4 r0, r1, r2, r3;
    r0.x = fmaf(a0.x, w0.x, b0.x * w1.x);
    r0.y = fmaf(a0.y, w0.y, b0.y * w1.y);
    r0.z = fmaf(a0.z, w0.z, b0.z * w1.z);
    r0.w = fmaf(a0.w, w0.w, b0.w * w1.w);
    r1.x = fmaf(a1.x, w0.x, b1.x * w1.x);
    r1.y = fmaf(a1.y, w0.y, b1.y * w1.y);
    r1.z = fmaf(a1.z, w0.z, b1.z * w1.z);
    r1.w = fmaf(a1.w, w0.w, b1.w * w1.w);
    r2.x = fmaf(a2.x, w0.x, b2.x * w1.x);
    r2.y = fmaf(a2.y, w0.y, b2.y * w1.y);
    r2.z = fmaf(a2.z, w0.z, b2.z * w1.z);
    r2.w = fmaf(a2.w, w0.w, b2.w * w1.w);
    r3.x = fmaf(a3.x, w0.x, b3.x * w1.x);
    r3.y = fmaf(a3.y, w0.y, b3.y * w1.y);
    r3.z = fmaf(a3.z, w0.z, b3.z * w1.z);
    r3.w = fmaf(a3.w, w0.w, b3.w * w1.w);

    float4* orow = out + (size_t)rq * (4 * D4) + d4;
    __stcs(orow + 0 * D4, r0);
    __stcs(orow + 1 * D4, r1);
    __stcs(orow + 2 * D4, r2);
    __stcs(orow + 3 * D4, r3);
}

extern "C" void kernel_launch(void* const* d_in, const int* in_sizes, int n_in,
                              void* d_out, int out_size)
{
    const float4* x = (const float4*)d_in[0];   // [B, N, D] fp32
    const float4* w = (const float4*)d_in[1];   // [P, D] fp32
    float4* out     = (float4*)d_out;           // [B, N/P, D] fp32

    int quad4  = out_size / 16;                 // output float4s / 4 rows-per-thread
    int blocks = (quad4 + THREADS - 1) / THREADS;

    nodeconv_kernel<<<blocks, THREADS>>>(x, w, out, quad4);
}